// round 2
// baseline (speedup 1.0000x reference)
#include <cuda_runtime.h>
#include <math.h>

// 9x9 max-dilation, SAME padding with -inf border (matches cv2.dilate /
// jax reduce_window SAME with -inf init). Separable:
//   stage 1: float4 global loads into smem raw tile (+ scalar halo)
//   stage 2: horizontal 9-max, 4 outputs/thread via log-step, LDS.128 reads
//   stage 3: vertical 9-max in registers, log-step sliding max
// Input 16x1024x1024x1 fp32.

#define IMG 1024
#define TW 128            // output tile width
#define TH 32             // output tile height
#define HALO 4
#define RW (TW + 2*HALO)  // 136 raw cols (544 B/row, 16B-aligned stride)
#define RH (TH + 2*HALO)  // 40 raw rows
#define NTHREADS 256
#define ROWS_PER_THREAD (TH / 2)   // 16: 256 threads = 128 cols x 2 row-groups

__global__ __launch_bounds__(NTHREADS)
void dilate9_kernel(const float* __restrict__ in, float* __restrict__ out) {
    __shared__ __align__(16) float raw[RH][RW];    // 21760 B
    __shared__ __align__(16) float hmax[RH][TW];   // 20480 B

    const int bx = blockIdx.x;       // tile col
    const int by = blockIdx.y;       // tile row
    const int bz = blockIdx.z;       // batch
    const int tid = threadIdx.x;

    const float* img = in  + (size_t)bz * IMG * IMG;
    float*      oimg = out + (size_t)bz * IMG * IMG;

    const int x0 = bx * TW - HALO;
    const int y0 = by * TH - HALO;

    // ---- Stage 1a: interior (aligned 128-wide) as float4 ----
    #pragma unroll
    for (int i = tid; i < RH * (TW / 4); i += NTHREADS) {
        const int r = i >> 5;            // / 32
        const int q = i & 31;
        const int gy = y0 + r;
        float4 v = make_float4(-INFINITY, -INFINITY, -INFINITY, -INFINITY);
        if ((unsigned)gy < (unsigned)IMG)
            v = *(const float4*)(img + gy * IMG + bx * TW + q * 4);
        *(float4*)&raw[r][HALO + q * 4] = v;
    }
    // ---- Stage 1b: halo columns (8 per row), scalar ----
    #pragma unroll
    for (int i = tid; i < RH * 8; i += NTHREADS) {
        const int r = i >> 3;
        const int h = i & 7;
        const int c = (h < 4) ? h : (TW + h);   // cols 0..3 and 132..135
        const int gy = y0 + r;
        const int gx = x0 + c;
        float v = -INFINITY;
        if ((unsigned)gy < (unsigned)IMG && (unsigned)gx < (unsigned)IMG)
            v = img[gy * IMG + gx];
        raw[r][c] = v;
    }
    __syncthreads();

    // ---- Stage 2: horizontal 9-max, 4 outputs per thread (log-step) ----
    // thread item (r, j): outputs hmax[r][4j..4j+3] from raw[r][4j..4j+11]
    #pragma unroll
    for (int i = tid; i < RH * (TW / 4); i += NTHREADS) {
        const int r = i >> 5;
        const int j = i & 31;
        const int c0 = 4 * j;
        float4 a = *(const float4*)&raw[r][c0];
        float4 b = *(const float4*)&raw[r][c0 + 4];
        float4 d = *(const float4*)&raw[r][c0 + 8];
        float v0 = a.x, v1 = a.y, v2 = a.z, v3 = a.w;
        float v4 = b.x, v5 = b.y, v6 = b.z, v7 = b.w;
        float v8 = d.x, v9 = d.y, v10 = d.z, v11 = d.w;
        // m2
        float p0 = fmaxf(v0, v1),  p1 = fmaxf(v1, v2),  p2 = fmaxf(v2, v3);
        float p3 = fmaxf(v3, v4),  p4 = fmaxf(v4, v5),  p5 = fmaxf(v5, v6);
        float p6 = fmaxf(v6, v7),  p7 = fmaxf(v7, v8),  p8 = fmaxf(v8, v9);
        float p9 = fmaxf(v9, v10), p10 = fmaxf(v10, v11);
        // m4
        float q0 = fmaxf(p0, p2), q1 = fmaxf(p1, p3), q2 = fmaxf(p2, p4);
        float q3 = fmaxf(p3, p5), q4 = fmaxf(p4, p6), q5 = fmaxf(p5, p7);
        float q6 = fmaxf(p6, p8), q7 = fmaxf(p7, p9), q8 = fmaxf(p8, p10);
        // m8
        float s0 = fmaxf(q0, q4), s1 = fmaxf(q1, q5);
        float s2 = fmaxf(q2, q6), s3 = fmaxf(q3, q7);
        float s4 = fmaxf(q4, q8); (void)s4;
        // out[k] = max(m8[k], v[k+8])
        float4 o;
        o.x = fmaxf(s0, v8);
        o.y = fmaxf(s1, v9);
        o.z = fmaxf(s2, v10);
        o.w = fmaxf(s3, v11);
        *(float4*)&hmax[r][c0] = o;
    }
    __syncthreads();

    // ---- Stage 3: vertical 9-max in registers (log-step sliding max) ----
    const int c  = tid & (TW - 1);               // 0..127
    const int rg = tid >> 7;                      // 0 or 1
    const int r0 = rg * ROWS_PER_THREAD;          // 0 or 16

    float v[ROWS_PER_THREAD + 8];
    #pragma unroll
    for (int k = 0; k < ROWS_PER_THREAD + 8; k++)
        v[k] = hmax[r0 + k][c];

    float m2[ROWS_PER_THREAD + 7];
    #pragma unroll
    for (int k = 0; k < ROWS_PER_THREAD + 7; k++) m2[k] = fmaxf(v[k], v[k + 1]);
    float m4[ROWS_PER_THREAD + 5];
    #pragma unroll
    for (int k = 0; k < ROWS_PER_THREAD + 5; k++) m4[k] = fmaxf(m2[k], m2[k + 2]);
    float m8[ROWS_PER_THREAD + 1];
    #pragma unroll
    for (int k = 0; k < ROWS_PER_THREAD + 1; k++) m8[k] = fmaxf(m4[k], m4[k + 4]);

    const int oy0 = by * TH + r0;
    const int ox  = bx * TW + c;
    #pragma unroll
    for (int k = 0; k < ROWS_PER_THREAD; k++) {
        const float o = fmaxf(m8[k], v[k + 8]);
        oimg[(oy0 + k) * IMG + ox] = o;
    }
}

extern "C" void kernel_launch(void* const* d_in, const int* in_sizes, int n_in,
                              void* d_out, int out_size) {
    const float* in = (const float*)d_in[0];
    float* out = (float*)d_out;
    const int batch = in_sizes[0] / (IMG * IMG);
    dim3 grid(IMG / TW, IMG / TH, batch);
    dilate9_kernel<<<grid, NTHREADS>>>(in, out);
}

// round 3
// speedup vs baseline: 1.1250x; 1.1250x over previous
#include <cuda_runtime.h>
#include <math.h>

// 9x9 max-dilation, SAME padding with -inf border.
// Separable, smem-minimal:
//   stage H: one warp per row; LDG.128 per lane (4 cols), horizontal 9-max via
//            prefix/suffix maxes + warp shuffles; edge lanes patch from two
//            predicated halo loads. Result -> hmax smem (only smem buffer).
//   stage V: vertical 9-max in registers (log-step sliding max), scalar LDS
//            (consecutive lanes, conflict-free), STG out.
// Input 16x1024x1024x1 fp32.

#define IMG 1024
#define TW 128            // output tile width (one warp: 32 lanes x 4 cols)
#define TH 32             // output tile height
#define HALO 4
#define RH (TH + 2*HALO)  // 40 hmax rows
#define NTHREADS 256
#define NWARPS (NTHREADS / 32)
#define ROWS_PER_THREAD (TH / 2)   // 16

__global__ __launch_bounds__(NTHREADS)
void dilate9_kernel(const float* __restrict__ in, float* __restrict__ out) {
    __shared__ __align__(16) float hmax[RH][TW];   // 20480 B

    const int bx = blockIdx.x;       // tile col (0..7)
    const int by = blockIdx.y;       // tile row (0..31)
    const int bz = blockIdx.z;       // batch
    const int tid  = threadIdx.x;
    const int lane = tid & 31;
    const int wid  = tid >> 5;

    const float* img = in  + (size_t)bz * IMG * IMG;
    float*      oimg = out + (size_t)bz * IMG * IMG;

    const int xbase = bx * TW;            // first interior col of tile
    const int y0 = by * TH - HALO;        // first hmax row (global y)
    const float NEG = -INFINITY;

    // ---- Stage H: horizontal 9-max, one warp per row ----
    #pragma unroll
    for (int r = wid; r < RH; r += NWARPS) {
        const int gy = y0 + r;
        const bool inrow = (unsigned)gy < (unsigned)IMG;

        float4 v = make_float4(NEG, NEG, NEG, NEG);
        if (inrow)
            v = *(const float4*)(img + gy * IMG + xbase + lane * 4);

        // halo loads for edge lanes
        float4 hl = make_float4(NEG, NEG, NEG, NEG);
        float4 hr = make_float4(NEG, NEG, NEG, NEG);
        if (lane == 0 && inrow && bx > 0)
            hl = *(const float4*)(img + gy * IMG + xbase - 4);
        if (lane == 31 && inrow && bx < (IMG / TW) - 1)
            hr = *(const float4*)(img + gy * IMG + xbase + TW);

        // prefix maxes p_k = max(v0..vk), suffix maxes s_k = max(vk..v3)
        const float p0 = v.x;
        const float p1 = fmaxf(p0, v.y);
        const float p2 = fmaxf(p1, v.z);
        const float p3 = fmaxf(p2, v.w);
        const float s3 = v.w;
        const float s2 = fmaxf(v.z, s3);
        const float s1 = fmaxf(v.y, s2);
        const float s0 = p3;             // max of all 4

        // neighbors: left suffixes (shfl up), right prefixes (shfl down)
        float sU0 = __shfl_up_sync(0xffffffffu, s0, 1);
        float sU1 = __shfl_up_sync(0xffffffffu, s1, 1);
        float sU2 = __shfl_up_sync(0xffffffffu, s2, 1);
        float sU3 = __shfl_up_sync(0xffffffffu, s3, 1);
        float pD0 = __shfl_down_sync(0xffffffffu, p0, 1);
        float pD1 = __shfl_down_sync(0xffffffffu, p1, 1);
        float pD2 = __shfl_down_sync(0xffffffffu, p2, 1);
        float pD3 = __shfl_down_sync(0xffffffffu, p3, 1);

        if (lane == 0) {   // left halo chunk hl (cols xbase-4..xbase-1)
            sU3 = hl.w;
            sU2 = fmaxf(hl.z, sU3);
            sU1 = fmaxf(hl.y, sU2);
            sU0 = fmaxf(hl.x, sU1);
        }
        if (lane == 31) {  // right halo chunk hr (cols xbase+128..131)
            pD0 = hr.x;
            pD1 = fmaxf(pD0, hr.y);
            pD2 = fmaxf(pD1, hr.z);
            pD3 = fmaxf(pD2, hr.w);
        }

        // out_k over window cols [4*lane + k - 4, 4*lane + k + 4]
        float4 o;
        o.x = fmaxf(fmaxf(sU0, s0), pD0);
        o.y = fmaxf(fmaxf(sU1, s0), pD1);
        o.z = fmaxf(fmaxf(sU2, s0), pD2);
        o.w = fmaxf(fmaxf(sU3, s0), pD3);
        *(float4*)&hmax[r][lane * 4] = o;
    }
    __syncthreads();

    // ---- Stage V: vertical 9-max in registers (log-step sliding max) ----
    const int c  = tid & (TW - 1);               // 0..127
    const int rg = tid >> 7;                      // 0 or 1
    const int r0 = rg * ROWS_PER_THREAD;          // 0 or 16

    float v[ROWS_PER_THREAD + 8];
    #pragma unroll
    for (int k = 0; k < ROWS_PER_THREAD + 8; k++)
        v[k] = hmax[r0 + k][c];

    float m2[ROWS_PER_THREAD + 7];
    #pragma unroll
    for (int k = 0; k < ROWS_PER_THREAD + 7; k++) m2[k] = fmaxf(v[k], v[k + 1]);
    float m4[ROWS_PER_THREAD + 5];
    #pragma unroll
    for (int k = 0; k < ROWS_PER_THREAD + 5; k++) m4[k] = fmaxf(m2[k], m2[k + 2]);
    float m8[ROWS_PER_THREAD + 1];
    #pragma unroll
    for (int k = 0; k < ROWS_PER_THREAD + 1; k++) m8[k] = fmaxf(m4[k], m4[k + 4]);

    const int oy0 = by * TH + r0;
    const int ox  = bx * TW + c;
    #pragma unroll
    for (int k = 0; k < ROWS_PER_THREAD; k++) {
        const float o = fmaxf(m8[k], v[k + 8]);
        oimg[(oy0 + k) * IMG + ox] = o;
    }
}

extern "C" void kernel_launch(void* const* d_in, const int* in_sizes, int n_in,
                              void* d_out, int out_size) {
    const float* in = (const float*)d_in[0];
    float* out = (float*)d_out;
    const int batch = in_sizes[0] / (IMG * IMG);
    dim3 grid(IMG / TW, IMG / TH, batch);
    dilate9_kernel<<<grid, NTHREADS>>>(in, out);
}